// round 2
// baseline (speedup 1.0000x reference)
#include <cuda_runtime.h>
#include <math.h>

// Problem dims (fixed for this problem instance)
#define BATCH 4
#define SEQ   4096
#define DDIM  1024
#define HDIM  1024
#define MROWS (BATCH*SEQ)     // 16384
#define NCH   32              // cumsum chunks per sequence
#define CH    (SEQ/NCH)       // 128 rows per chunk
static_assert(NCH == 32, "chunk index math assumes NCH==32");

// Scratch (device globals: no allocations allowed)
__device__ float g_U[(size_t)MROWS * HDIM];          // iV@W1, then h1 (in-place)
__device__ float g_H[(size_t)MROWS * DDIM];          // h = h1@W2 + b2
__device__ float g_part[BATCH * NCH * HDIM];         // chunk partial sums

// ---------------------------------------------------------------------------
// SGEMM: C[M,N] = A[M,K] @ B[K,N] (+bias) with optional fused gate epilogue
//   MODE 0: g_U = A@B                     (U = iV @ W1)
//   MODE 1: g_H = g_U@B + bias            (h = h1 @ W2 + b2)
//   MODE 2: gate GEMM, A-source switches iQ->g_H at k=1024; B columns
//           interleaved (even j -> igate col, odd j -> fgate col) so each
//           thread holds matching gate pairs; epilogue computes
//           out = sigmoid(zi)*iQ + sigmoid(zf)*h  directly.
// Tiles: BM=BN=128, BK=16, 256 threads, 8x8 accumulator per thread.
// ---------------------------------------------------------------------------
#define BM 128
#define BN 128
#define BK 16
#define TM 8
#define TN 8

template<int MODE>
__global__ __launch_bounds__(256)
void sgemm(const float* __restrict__ A,    // mode0: iV ; mode2: iQ
           const float* __restrict__ B,
           const float* __restrict__ bias, // mode1: b2 ; mode2: bg
           float* __restrict__ Cout)       // mode2: d_out
{
    __shared__ float As[BK][BM];
    __shared__ float Bs[BK][BN];

    const float* Asrc0 = (MODE == 1) ? g_U : A;   // primary A source
    const float* Ah    = g_H;                      // mode2 second A source
    float* C = (MODE == 0) ? g_U : (MODE == 1) ? g_H : Cout;
    const int K   = (MODE == 2) ? 2 * DDIM : DDIM;
    const int ldb = (MODE == 2) ? 2 * DDIM : HDIM;

    const int tid = threadIdx.x;
    const int tx = tid & 15;          // 0..15 (col group)
    const int ty = tid >> 4;          // 0..15 (row group)
    const int bx = blockIdx.x;
    const int by = blockIdx.y;
    const int rowBase = by * BM;

    // A-tile load mapping: 2 x float4 per thread
    const int aRow = tid >> 2;        // 0..63
    const int aCol = (tid & 3) * 4;   // 0,4,8,12
    // B-tile load mapping (modes 0/1): 2 x float4 per thread
    const int bRow = tid >> 5;        // 0..7
    const int bCol = (tid & 31) * 4;  // 0..124

    float acc[TM][TN];
    #pragma unroll
    for (int i = 0; i < TM; i++)
        #pragma unroll
        for (int j = 0; j < TN; j++) acc[i][j] = 0.f;

    for (int kt = 0; kt < K; kt += BK) {
        // ---- load A tile (transposed into smem) ----
        const float* Asrc;
        int ac;
        if (MODE == 2) {
            if (kt < DDIM) { Asrc = Asrc0; ac = kt + aCol; }
            else           { Asrc = Ah;    ac = kt - DDIM + aCol; }
        } else { Asrc = Asrc0; ac = kt + aCol; }

        float4 a0 = *(const float4*)&Asrc[(size_t)(rowBase + aRow)      * DDIM + ac];
        float4 a1 = *(const float4*)&Asrc[(size_t)(rowBase + aRow + 64) * DDIM + ac];
        As[aCol + 0][aRow] = a0.x; As[aCol + 1][aRow] = a0.y;
        As[aCol + 2][aRow] = a0.z; As[aCol + 3][aRow] = a0.w;
        As[aCol + 0][aRow + 64] = a1.x; As[aCol + 1][aRow + 64] = a1.y;
        As[aCol + 2][aRow + 64] = a1.z; As[aCol + 3][aRow + 64] = a1.w;

        // ---- load B tile ----
        if (MODE != 2) {
            float4 b0 = *(const float4*)&B[(size_t)(kt + bRow)     * ldb + bx * BN + bCol];
            float4 b1 = *(const float4*)&B[(size_t)(kt + bRow + 8) * ldb + bx * BN + bCol];
            Bs[bRow][bCol + 0] = b0.x; Bs[bRow][bCol + 1] = b0.y;
            Bs[bRow][bCol + 2] = b0.z; Bs[bRow][bCol + 3] = b0.w;
            Bs[bRow + 8][bCol + 0] = b1.x; Bs[bRow + 8][bCol + 1] = b1.y;
            Bs[bRow + 8][bCol + 2] = b1.z; Bs[bRow + 8][bCol + 3] = b1.w;
        } else {
            // interleaved gate columns: even j -> Wg[:, bx*64 + j/2]
            //                            odd j -> Wg[:, 1024 + bx*64 + j/2]
            #pragma unroll
            for (int i = 0; i < 8; i++) {
                int e = tid + i * 256;        // 0..2047
                int k = e >> 7;               // 0..15
                int j = e & 127;              // 0..127
                int col = ((j & 1) ? DDIM : 0) + bx * 64 + (j >> 1);
                Bs[k][j] = B[(size_t)(kt + k) * ldb + col];
            }
        }
        __syncthreads();

        // ---- FMA mainloop ----
        #pragma unroll
        for (int k = 0; k < BK; k++) {
            float a[TM], b[TN];
            #pragma unroll
            for (int i = 0; i < TM; i++) a[i] = As[k][ty * TM + i];
            #pragma unroll
            for (int j = 0; j < TN; j++) b[j] = Bs[k][tx * TN + j];
            #pragma unroll
            for (int i = 0; i < TM; i++)
                #pragma unroll
                for (int j = 0; j < TN; j++)
                    acc[i][j] += a[i] * b[j];
        }
        __syncthreads();
    }

    // ---- epilogue ----
    if (MODE == 0 || MODE == 1) {
        #pragma unroll
        for (int i = 0; i < TM; i++) {
            int row = rowBase + ty * TM + i;
            int col = bx * BN + tx * TN;
            float4 v0, v1;
            if (MODE == 1) {
                v0.x = acc[i][0] + bias[col + 0]; v0.y = acc[i][1] + bias[col + 1];
                v0.z = acc[i][2] + bias[col + 2]; v0.w = acc[i][3] + bias[col + 3];
                v1.x = acc[i][4] + bias[col + 4]; v1.y = acc[i][5] + bias[col + 5];
                v1.z = acc[i][6] + bias[col + 6]; v1.w = acc[i][7] + bias[col + 7];
            } else {
                v0.x = acc[i][0]; v0.y = acc[i][1]; v0.z = acc[i][2]; v0.w = acc[i][3];
                v1.x = acc[i][4]; v1.y = acc[i][5]; v1.z = acc[i][6]; v1.w = acc[i][7];
            }
            *(float4*)&C[(size_t)row * DDIM + col]     = v0;
            *(float4*)&C[(size_t)row * DDIM + col + 4] = v1;
        }
    } else {
        #pragma unroll
        for (int i = 0; i < TM; i++) {
            int row = rowBase + ty * TM + i;
            #pragma unroll
            for (int p = 0; p < 4; p++) {
                int dcol = bx * 64 + tx * 4 + p;
                float zi = acc[i][2 * p]     + bias[dcol];
                float zf = acc[i][2 * p + 1] + bias[DDIM + dcol];
                float si = 1.f / (1.f + __expf(-zi));
                float sf = 1.f / (1.f + __expf(-zf));
                float q  = Asrc0[(size_t)row * DDIM + dcol];
                float hh = Ah   [(size_t)row * DDIM + dcol];
                C[(size_t)row * DDIM + dcol] = si * q + sf * hh;
            }
        }
    }
}

// ---------------------------------------------------------------------------
// Chunked prefix-mean over U (axis s), fused + b1 + ReLU, in place.
// ---------------------------------------------------------------------------
__global__ void chunk_sum()
{
    int d = blockIdx.x * 256 + threadIdx.x;
    int bc = blockIdx.y;                 // 0..BATCH*NCH-1
    int b = bc >> 5, c = bc & (NCH - 1);
    const float* p = g_U + ((size_t)b * SEQ + c * CH) * HDIM + d;
    float s = 0.f;
    #pragma unroll 4
    for (int i = 0; i < CH; i++) s += p[(size_t)i * HDIM];
    g_part[(b * NCH + c) * HDIM + d] = s;
}

__global__ void chunk_scan()
{
    int d = blockIdx.x * 256 + threadIdx.x;
    int b = blockIdx.y;
    float ex = 0.f;
    #pragma unroll
    for (int c = 0; c < NCH; c++) {
        size_t idx = (size_t)(b * NCH + c) * HDIM + d;
        float t = g_part[idx];
        g_part[idx] = ex;
        ex += t;
    }
}

__global__ void chunk_apply(const float* __restrict__ b1)
{
    int d = blockIdx.x * 256 + threadIdx.x;
    int bc = blockIdx.y;
    int b = bc >> 5, c = bc & (NCH - 1);
    float run = g_part[(b * NCH + c) * HDIM + d];
    float bb = b1[d];
    float* p = g_U + ((size_t)b * SEQ + c * CH) * HDIM + d;
    #pragma unroll 4
    for (int i = 0; i < CH; i++) {
        run += p[(size_t)i * HDIM];
        float v = run / (float)(c * CH + i + 1) + bb;
        p[(size_t)i * HDIM] = v > 0.f ? v : 0.f;
    }
}

// ---------------------------------------------------------------------------
extern "C" void kernel_launch(void* const* d_in, const int* in_sizes, int n_in,
                              void* d_out, int out_size)
{
    const float* iQ = (const float*)d_in[0];
    const float* iV = (const float*)d_in[1];
    const float* W1 = (const float*)d_in[2];
    const float* b1 = (const float*)d_in[3];
    const float* W2 = (const float*)d_in[4];
    const float* b2 = (const float*)d_in[5];
    const float* Wg = (const float*)d_in[6];
    const float* bg = (const float*)d_in[7];
    float* out = (float*)d_out;

    // 1) U = iV @ W1   (cumsum commutes: avg@W1 = cumsum(iV@W1)/denom)
    sgemm<0><<<dim3(HDIM / BN, MROWS / BM), 256>>>(iV, W1, nullptr, nullptr);
    // 2) h1 = relu(cumsum(U)/denom + b1), in place in U
    chunk_sum  <<<dim3(HDIM / 256, BATCH * NCH), 256>>>();
    chunk_scan <<<dim3(HDIM / 256, BATCH),       256>>>();
    chunk_apply<<<dim3(HDIM / 256, BATCH * NCH), 256>>>(b1);
    // 3) h = h1 @ W2 + b2
    sgemm<1><<<dim3(DDIM / BN, MROWS / BM), 256>>>(nullptr, W2, b2, nullptr);
    // 4) out = sigmoid([iQ h]@Wg + bg) gates applied to (iQ, h), fused epilogue
    sgemm<2><<<dim3(DDIM / 64, MROWS / BM), 256>>>(iQ, Wg, bg, out);
}

// round 4
// speedup vs baseline: 2.0152x; 2.0152x over previous
#include <cuda_runtime.h>
#include <cuda_bf16.h>
#include <cstdint>
#include <math.h>

// ---------------------------------------------------------------------------
#define BATCH 4
#define SEQ   4096
#define DDIM  1024
#define MROWS (BATCH*SEQ)     // 16384
#define NCH   32
#define CH    (SEQ/NCH)       // 128

// Device scratch (no allocations allowed)
__device__ float g_U[(size_t)MROWS * DDIM];            // GEMM1 out -> h1 (in place)
__device__ float g_H[(size_t)MROWS * DDIM];            // GEMM2 out (h)
__device__ float g_part[BATCH * NCH * DDIM];
__device__ __nv_bfloat16 g_S1[(size_t)MROWS * 2048];   // split act: Vs -> h1s -> Hs
__device__ __nv_bfloat16 g_S2[(size_t)MROWS * 2048];   // split act: Qs
__device__ __nv_bfloat16 g_W1t[(size_t)1024 * 2048];   // W1^T split [N, 2K]
__device__ __nv_bfloat16 g_W2t[(size_t)1024 * 2048];
__device__ __nv_bfloat16 g_Wgt[(size_t)2048 * 4096];   // Wg^T split, gate-interleaved rows

// ---------------------------------------------------------------------------
// PTX helpers (sm_100-safe: cp.async / ldmatrix / mma.sync only)
// ---------------------------------------------------------------------------
__device__ __forceinline__ uint32_t smem_to_u32(const void* p) {
    uint32_t a;
    asm("{ .reg .u64 t; cvta.to.shared.u64 t, %1; cvt.u32.u64 %0, t; }" : "=r"(a) : "l"(p));
    return a;
}
__device__ __forceinline__ void cp16(uint32_t dst, const void* src) {
    asm volatile("{\n\t.reg .u64 g;\n\tcvta.to.global.u64 g, %1;\n\t"
                 "cp.async.cg.shared.global [%0], [g], 16;\n\t}"
                 :: "r"(dst), "l"(src));
}
#define CP_COMMIT() asm volatile("cp.async.commit_group;" ::: "memory")
#define CP_WAIT1()  asm volatile("cp.async.wait_group 1;" ::: "memory")
#define CP_WAIT0()  asm volatile("cp.async.wait_group 0;" ::: "memory")

__device__ __forceinline__ void ldsm4(uint32_t* r, uint32_t a) {
    asm volatile("ldmatrix.sync.aligned.m8n8.x4.shared.b16 {%0,%1,%2,%3}, [%4];"
                 : "=r"(r[0]), "=r"(r[1]), "=r"(r[2]), "=r"(r[3]) : "r"(a));
}
__device__ __forceinline__ void mma16816(float* c, const uint32_t* a, const uint32_t* b) {
    asm volatile("mma.sync.aligned.m16n8k16.row.col.f32.bf16.bf16.f32 "
                 "{%0,%1,%2,%3}, {%4,%5,%6,%7}, {%8,%9}, {%0,%1,%2,%3};"
                 : "+f"(c[0]), "+f"(c[1]), "+f"(c[2]), "+f"(c[3])
                 : "r"(a[0]), "r"(a[1]), "r"(a[2]), "r"(a[3]), "r"(b[0]), "r"(b[1]));
}

// ---------------------------------------------------------------------------
// Conversions: fp32 -> (hi | lo) bf16 planes
// ---------------------------------------------------------------------------
__global__ __launch_bounds__(256) void split_act(const float* __restrict__ X,
                                                 __nv_bfloat16* __restrict__ Y)
{
    size_t i = ((size_t)blockIdx.x * 256 + threadIdx.x) * 4;
    size_t row = i >> 10;
    int col = (int)(i & 1023);
    float4 v = *(const float4*)(X + i);
    __nv_bfloat16 h0 = __float2bfloat16(v.x), h1 = __float2bfloat16(v.y);
    __nv_bfloat16 h2 = __float2bfloat16(v.z), h3 = __float2bfloat16(v.w);
    __nv_bfloat16 l0 = __float2bfloat16(v.x - __bfloat162float(h0));
    __nv_bfloat16 l1 = __float2bfloat16(v.y - __bfloat162float(h1));
    __nv_bfloat16 l2 = __float2bfloat16(v.z - __bfloat162float(h2));
    __nv_bfloat16 l3 = __float2bfloat16(v.w - __bfloat162float(h3));
    __nv_bfloat162* ph = (__nv_bfloat162*)(Y + row * 2048 + col);
    ph[0] = __nv_bfloat162(h0, h1); ph[1] = __nv_bfloat162(h2, h3);
    __nv_bfloat162* pl = (__nv_bfloat162*)(Y + row * 2048 + 1024 + col);
    pl[0] = __nv_bfloat162(l0, l1); pl[1] = __nv_bfloat162(l2, l3);
}

// W [K,N] fp32 -> Wt [N', 2K] bf16 (hi|lo), transposed; optional gate interleave
// (inter: n' = n<N/2 ? 2n : 2(n-N/2)+1  so igate/fgate cols become adjacent)
__global__ __launch_bounds__(256) void split_w_t(const float* __restrict__ W,
                                                 __nv_bfloat16* __restrict__ Wt,
                                                 int K, int N, int inter)
{
    __shared__ float t[32][33];
    int n0 = blockIdx.x * 32, k0 = blockIdx.y * 32;
    int tx = threadIdx.x & 31, ty = threadIdx.x >> 5;
    #pragma unroll
    for (int i = 0; i < 32; i += 8)
        t[ty + i][tx] = W[(size_t)(k0 + ty + i) * N + n0 + tx];
    __syncthreads();
    #pragma unroll
    for (int i = 0; i < 32; i += 8) {
        float v = t[tx][ty + i];
        int n = n0 + ty + i, k = k0 + tx;
        int nd = inter ? ((n < N / 2) ? 2 * n : 2 * (n - N / 2) + 1) : n;
        __nv_bfloat16 h = __float2bfloat16(v);
        Wt[(size_t)nd * (2 * K) + k]     = h;
        Wt[(size_t)nd * (2 * K) + K + k] = __float2bfloat16(v - __bfloat162float(h));
    }
}

// ---------------------------------------------------------------------------
// mma.sync GEMM, bf16x3 (hi*hi + lo*hi + hi*lo), fp32 accum.
//   MODE 0: g_U = Vs  @ W1t^T
//   MODE 1: g_H = h1s @ W2t^T + b2
//   MODE 2: out = sigmoid([Qs Hs] @ Wgt^T + bg) gate-mix, fused (interleaved cols)
// CTA 128x128, BK=32, 8 warps (2x4), warp tile 64x32, double-buffered cp.async.
// ---------------------------------------------------------------------------
#define LDT 40                 // smem row pitch in bf16 (80B) -> conflict-free ldmatrix
#define TILE_SM (128*LDT)      // elems per tile buffer

template<int MODE>
__global__ __launch_bounds__(256)
void gemm_mma(const float* __restrict__ bias,   // mode1: b2, mode2: bg
              const float* __restrict__ Q,      // mode2: iQ (epilogue)
              float* __restrict__ Cout)         // mode2: d_out
{
    __shared__ __align__(16) __nv_bfloat16 sA[2][TILE_SM];
    __shared__ __align__(16) __nv_bfloat16 sB[2][TILE_SM];

    const int tid = threadIdx.x, lane = tid & 31, wid = tid >> 5;
    const int wr = wid >> 2, wc = wid & 3;          // warp grid 2 x 4
    const int bx = blockIdx.x, by = blockIdx.y;
    const int rowBase = by * 128;

    const __nv_bfloat16* Bw = (MODE == 0) ? g_W1t : (MODE == 1) ? g_W2t : g_Wgt;
    const int KC = (MODE == 2) ? 64 : 32;           // 32-wide chunks per phase
    const int NC = 3 * KC;
    const size_t ldb = (MODE == 2) ? 4096 : 2048;

    const uint32_t uA = smem_to_u32(sA);
    const uint32_t uB = smem_to_u32(sB);

    // cp.async staging mapping: 512 chunks of 16B per tile, 2 per thread
    const int sr = tid >> 2;            // 0..63  (row pair base; +64 for t=1)
    const int sc = (tid & 3) * 8;       // bf16 col: 0,8,16,24

    // ldmatrix per-lane offsets
    const int rA  = (lane & 7) + ((lane >> 3) & 1) * 8;   // A: tile bit0 -> +8 rows
    const int cA8 = (lane >> 4) * 8;                      //    tile bit1 -> +8 k
    const int rB  = (lane & 7) + ((lane >> 4) & 1) * 8;   // B: bit1 -> +8 n
    const int cB8 = ((lane >> 3) & 1) * 8;                //    bit0 -> +8 k
    const uint32_t aOff = (uint32_t)(((wr * 64 + rA) * LDT + cA8) * 2);
    const uint32_t bOff = (uint32_t)(((wc * 32 + rB) * LDT + cB8) * 2);

    float acc[4][4][4];
    #pragma unroll
    for (int mt = 0; mt < 4; mt++)
        #pragma unroll
        for (int nt = 0; nt < 4; nt++)
            #pragma unroll
            for (int p = 0; p < 4; p++) acc[mt][nt][p] = 0.f;

    // stage chunk cc into buffer cc&1
    auto stage = [&](int cc) {
        int phase = cc / KC;
        int kk = (cc % KC) * 32;
        int aoff = (phase == 1) ? 1024 : 0;
        const __nv_bfloat16* As;
        if (MODE == 2)
            As = (kk < 1024) ? (g_S2 + aoff + kk) : (g_S1 + aoff + (kk - 1024));
        else
            As = g_S1 + aoff + kk;
        As += (size_t)rowBase * 2048;
        int boff = (phase == 2) ? ((MODE == 2) ? 2048 : 1024) : 0;
        const __nv_bfloat16* Bs = Bw + (size_t)(bx * 128) * ldb + boff + kk;
        int buf = cc & 1;
        uint32_t dA = uA + (uint32_t)(buf * TILE_SM * 2);
        uint32_t dB = uB + (uint32_t)(buf * TILE_SM * 2);
        #pragma unroll
        for (int t = 0; t < 2; t++) {
            int r = sr + t * 64;
            cp16(dA + (uint32_t)((r * LDT + sc) * 2), As + (size_t)r * 2048 + sc);
            cp16(dB + (uint32_t)((r * LDT + sc) * 2), Bs + (size_t)r * ldb  + sc);
        }
    };

    stage(0); CP_COMMIT();

    for (int cc = 0; cc < NC; cc++) {
        if (cc + 1 < NC) { stage(cc + 1); CP_COMMIT(); CP_WAIT1(); }
        else             { CP_WAIT0(); }
        __syncthreads();

        const uint32_t bufB = (uint32_t)((cc & 1) * TILE_SM * 2);
        #pragma unroll
        for (int ks = 0; ks < 2; ks++) {
            uint32_t a[4][4], b[2][4];
            #pragma unroll
            for (int mt = 0; mt < 4; mt++)
                ldsm4(a[mt], uA + bufB + aOff + (uint32_t)(mt * 16 * LDT * 2 + ks * 32));
            #pragma unroll
            for (int np = 0; np < 2; np++)
                ldsm4(b[np], uB + bufB + bOff + (uint32_t)(np * 16 * LDT * 2 + ks * 32));
            #pragma unroll
            for (int mt = 0; mt < 4; mt++)
                #pragma unroll
                for (int nt = 0; nt < 4; nt++)
                    mma16816(acc[mt][nt], a[mt], &b[nt >> 1][(nt & 1) * 2]);
        }
        __syncthreads();
    }

    // ---- epilogue ----
    #pragma unroll
    for (int mt = 0; mt < 4; mt++) {
        int r0 = rowBase + wr * 64 + mt * 16 + (lane >> 2);
        #pragma unroll
        for (int nt = 0; nt < 4; nt++) {
            int col = bx * 128 + wc * 32 + nt * 8 + (lane & 3) * 2;
            float* a4 = acc[mt][nt];
            if (MODE == 0) {
                *(float2*)(g_U + (size_t)r0 * DDIM + col)       = make_float2(a4[0], a4[1]);
                *(float2*)(g_U + (size_t)(r0 + 8) * DDIM + col) = make_float2(a4[2], a4[3]);
            } else if (MODE == 1) {
                float b0 = bias[col], b1 = bias[col + 1];
                *(float2*)(g_H + (size_t)r0 * DDIM + col)       = make_float2(a4[0] + b0, a4[1] + b1);
                *(float2*)(g_H + (size_t)(r0 + 8) * DDIM + col) = make_float2(a4[2] + b0, a4[3] + b1);
            } else {
                int d = col >> 1;                  // interleave: even=igate, odd=fgate
                float bi = bias[d], bf = bias[DDIM + d];
                #pragma unroll
                for (int h2 = 0; h2 < 2; h2++) {
                    int r = r0 + h2 * 8;
                    float zi = a4[2 * h2]     + bi;
                    float zf = a4[2 * h2 + 1] + bf;
                    float si = 1.f / (1.f + __expf(-zi));
                    float sf = 1.f / (1.f + __expf(-zf));
                    float qv = Q  [(size_t)r * DDIM + d];
                    float hv = g_H[(size_t)r * DDIM + d];
                    Cout[(size_t)r * DDIM + d] = si * qv + sf * hv;
                }
            }
        }
    }
}

// ---------------------------------------------------------------------------
// Chunked prefix-mean (+b1, ReLU) on g_U, in place
// ---------------------------------------------------------------------------
__global__ void chunk_sum()
{
    int d = blockIdx.x * 256 + threadIdx.x;
    int bc = blockIdx.y;
    int b = bc >> 5, c = bc & (NCH - 1);
    const float* p = g_U + ((size_t)b * SEQ + c * CH) * DDIM + d;
    float s = 0.f;
    #pragma unroll 4
    for (int i = 0; i < CH; i++) s += p[(size_t)i * DDIM];
    g_part[(b * NCH + c) * DDIM + d] = s;
}
__global__ void chunk_scan()
{
    int d = blockIdx.x * 256 + threadIdx.x;
    int b = blockIdx.y;
    float ex = 0.f;
    #pragma unroll
    for (int c = 0; c < NCH; c++) {
        size_t idx = (size_t)(b * NCH + c) * DDIM + d;
        float t = g_part[idx];
        g_part[idx] = ex;
        ex += t;
    }
}
__global__ void chunk_apply(const float* __restrict__ b1)
{
    int d = blockIdx.x * 256 + threadIdx.x;
    int bc = blockIdx.y;
    int b = bc >> 5, c = bc & (NCH - 1);
    float run = g_part[(b * NCH + c) * DDIM + d];
    float bb = b1[d];
    float* p = g_U + ((size_t)b * SEQ + c * CH) * DDIM + d;
    #pragma unroll 4
    for (int i = 0; i < CH; i++) {
        run += p[(size_t)i * DDIM];
        float v = run / (float)(c * CH + i + 1) + bb;
        p[(size_t)i * DDIM] = v > 0.f ? v : 0.f;
    }
}

// ---------------------------------------------------------------------------
extern "C" void kernel_launch(void* const* d_in, const int* in_sizes, int n_in,
                              void* d_out, int out_size)
{
    const float* iQ = (const float*)d_in[0];
    const float* iV = (const float*)d_in[1];
    const float* W1 = (const float*)d_in[2];
    const float* b1 = (const float*)d_in[3];
    const float* W2 = (const float*)d_in[4];
    const float* b2 = (const float*)d_in[5];
    const float* Wg = (const float*)d_in[6];
    const float* bg = (const float*)d_in[7];
    float* out = (float*)d_out;

    float *U, *H;
    __nv_bfloat16 *S1, *S2, *W1t, *W2t, *Wgt;
    cudaGetSymbolAddress((void**)&U,   g_U);
    cudaGetSymbolAddress((void**)&H,   g_H);
    cudaGetSymbolAddress((void**)&S1,  g_S1);
    cudaGetSymbolAddress((void**)&S2,  g_S2);
    cudaGetSymbolAddress((void**)&W1t, g_W1t);
    cudaGetSymbolAddress((void**)&W2t, g_W2t);
    cudaGetSymbolAddress((void**)&Wgt, g_Wgt);

    const int SPLIT_BLK = (MROWS * DDIM / 4) / 256;   // 16384

    // weight conversions (independent of activations)
    split_w_t<<<dim3(1024/32, 1024/32), 256>>>(W1, W1t, 1024, 1024, 0);
    split_w_t<<<dim3(1024/32, 1024/32), 256>>>(W2, W2t, 1024, 1024, 0);
    split_w_t<<<dim3(2048/32, 2048/32), 256>>>(Wg, Wgt, 2048, 2048, 1);

    // 1) U = iV @ W1  (cumsum commutes with the K-contraction)
    split_act<<<SPLIT_BLK, 256>>>(iV, S1);
    gemm_mma<0><<<dim3(8, 128), 256>>>(nullptr, nullptr, nullptr);
    // 2) h1 = relu(cumsum(U)/denom + b1), in place
    chunk_sum  <<<dim3(DDIM/256, BATCH*NCH), 256>>>();
    chunk_scan <<<dim3(DDIM/256, BATCH),     256>>>();
    chunk_apply<<<dim3(DDIM/256, BATCH*NCH), 256>>>(b1);
    // 3) h = h1 @ W2 + b2
    split_act<<<SPLIT_BLK, 256>>>(U, S1);
    gemm_mma<1><<<dim3(8, 128), 256>>>(b2, nullptr, nullptr);
    // 4) fused gate GEMM (interleaved cols) + sigmoid gate-mix epilogue
    split_act<<<SPLIT_BLK, 256>>>(iQ, S2);
    split_act<<<SPLIT_BLK, 256>>>(H, S1);
    gemm_mma<2><<<dim3(16, 128), 256>>>(bg, iQ, out);
}